// round 14
// baseline (speedup 1.0000x reference)
#include <cuda_runtime.h>

#define HW    16384      // H*W
#define ROWS  4096       // B*C
#define CC    128
#define BB    32
#define TOPK  1638       // round(16384 * 0.1)
#define HID   8
#define NT    256
#define NWARP 8
#define SLOT  25         // per-thread candidate slots (64 elems/thread, ~10 hits)
#define STRIDE 26        // SLOT real slots + 1 dump slot
#define NBH   1792       // histogram bins (7/thread); valid ids [0,1536]
#define BUFN  256        // threshold-bin buffer
#define T_LO  1.0f
#define FONE  0x3F800000u

__device__ float g_avg[ROWS];
__device__ float g_maxv[ROWS];
__device__ float g_scale[ROWS];

__device__ __forceinline__ unsigned f2key(float f) {
    unsigned u = __float_as_uint(f);
    return u ^ ((unsigned)((int)u >> 31) | 0x80000000u);
}
__device__ __forceinline__ float key2f(unsigned k) {
    unsigned u = k ^ (((int)k < 0) ? 0x80000000u : 0xFFFFFFFFu);
    return __uint_as_float(u);
}
__device__ __forceinline__ int vbin(float v) {
    return min((int)((__float_as_uint(v) - FONE) >> 14), 1536);
}
// packed u16-pair histogram read: bin b lives in word b>>1, half b&1
__device__ __forceinline__ int hget(const unsigned* hp, int b) {
    return (int)((hp[b >> 1] >> ((b & 1) * 16)) & 0xFFFFu);
}

// Suffix-count select over packed hist: bin b with s(b) >= rem > s(b+1).
__device__ __forceinline__ void suffix_select_p(const unsigned* hp, int rem,
                                                int* swarp, unsigned* sdigit,
                                                int* srem) {
    const int tid = threadIdx.x, lane = tid & 31, w = tid >> 5;
    const int BPT = NBH / NT;            // 7 bins per thread
    const int base = tid * BPT;
    int loc[NBH / NT];
    int tsum = 0;
#pragma unroll
    for (int i = 0; i < BPT; i++) { loc[i] = hget(hp, base + i); tsum += loc[i]; }
    int inc = tsum;                       // suffix over lanes >= lane
#pragma unroll
    for (int o = 1; o < 32; o <<= 1) {
        int v = __shfl_down_sync(0xffffffffu, inc, o);
        if (lane + o < 32) inc += v;
    }
    if (lane == 0) swarp[w] = inc;
    __syncthreads();
    if (tid < 32) {
        int v = (lane < NWARP) ? swarp[lane] : 0;
        int s = v;
#pragma unroll
        for (int o = 1; o < 32; o <<= 1) {
            int t = __shfl_down_sync(0xffffffffu, s, o);
            if (lane + o < 32) s += t;
        }
        if (lane < NWARP) swarp[lane] = s - v;   // exclusive suffix above this warp
    }
    __syncthreads();
    int s_next = (inc - tsum) + swarp[w];
#pragma unroll
    for (int i = BPT - 1; i >= 0; i--) {
        int s = loc[i] + s_next;
        if (s >= rem && s_next < rem) { *sdigit = (unsigned)(base + i); *srem = rem - s_next; }
        s_next = s;
    }
    __syncthreads();
}

// ---------------------------------------------------------------------------
// Pass 1: per-(b,c) top-k mean + max.
// Sweep: branch-free dump-slot compaction. Post-pass: max + packed histogram.
// Then suffix-select + 14-bit in-bin binary search (warp 0).
// ---------------------------------------------------------------------------
__global__ __launch_bounds__(NT, 7) void topk_stats(const float* __restrict__ x) {
    __shared__ float    cand[NT * STRIDE];   // 26.6 KB per-thread segments (+dump)
    __shared__ unsigned histp[NBH / 2];      // 3.5 KB packed u16-pair histogram
    __shared__ unsigned buf[BUFN];           // 1 KB threshold-bin members (low 14 bits)
    __shared__ int      swarp[NWARP];
    __shared__ unsigned sdigit, suT;
    __shared__ int      srem, sfall, snb;
    __shared__ float    fred[NWARP];
    __shared__ int      ired[NWARP];

    const int tid = threadIdx.x, lane = tid & 31, w = tid >> 5;
    const int row = blockIdx.x;
    const float4* xin = (const float4*)(x + (size_t)row * HW);
    float* seg = cand + tid * STRIDE;

    // zero packed histogram (filled by post-pass)
#pragma unroll
    for (int i = tid; i < NBH / 2; i += NT) histp[i] = 0u;
    if (tid == 0) snb = 0;
    __syncthreads();

    // ---- sweep: branch-free compaction with dump slot ----
    int cnt = 0;
#pragma unroll 8
    for (int i = 0; i < HW / (4 * NT); i++) {
        float4 v = xin[tid + i * NT];
        int h0 = v.x > T_LO, h1 = v.y > T_LO, h2 = v.z > T_LO, h3 = v.w > T_LO;
        int p0 = cnt, p1 = p0 + h0, p2 = p1 + h1, p3 = p2 + h2;
        seg[h0 ? min(p0, SLOT) : SLOT] = v.x;
        seg[h1 ? min(p1, SLOT) : SLOT] = v.y;
        seg[h2 ? min(p2, SLOT) : SLOT] = v.z;
        seg[h3 ? min(p3, SLOT) : SLOT] = v.w;
        cnt = p3 + h3;
    }

    // ---- post-pass over real candidates: max + packed histogram ----
    const int mc = min(cnt, SLOT);
    float lmax = -3.402823466e38f;
    for (int i = 0; i < mc; i++) {
        float v = seg[i];
        lmax = fmaxf(lmax, v);
        int b = vbin(v);
        atomicAdd(&histp[b >> 1], (b & 1) ? 65536u : 1u);
    }

    int of = (cnt > SLOT) ? 1 : 0;
    int tot = cnt;
#pragma unroll
    for (int o = 16; o; o >>= 1) {
        lmax = fmaxf(lmax, __shfl_down_sync(0xffffffffu, lmax, o));
        tot += __shfl_down_sync(0xffffffffu, tot, o);
        of  |= __shfl_down_sync(0xffffffffu, of, o);
    }
    if (lane == 0) { fred[w] = lmax; ired[w] = tot; swarp[w] = of; }
    __syncthreads();
    if (tid == 0) {
        float m = fred[0]; int t = 0, o = 0;
        for (int i = 0; i < NWARP; i++) { m = fmaxf(m, fred[i]); t += ired[i]; o |= swarp[i]; }
        sfall = (o || t < TOPK);
        if (!sfall) g_maxv[row] = m;     // fast path: max is among candidates
    }
    __syncthreads();

    if (!sfall) {
        suffix_select_p(histp, TOPK, swarp, &sdigit, &srem);
        const unsigned d0 = sdigit; const int rem1 = srem;

        if (d0 >= 1536) { if (tid == 0) sfall = 1; }
        else {
            // collect threshold-bin members (low 14 bits) into buf
            for (int i = 0; i < mc; i++) {
                unsigned u = __float_as_uint(seg[i]);
                if ((u - FONE) >> 14 == d0) {
                    int p = atomicAdd(&snb, 1);
                    if (p < BUFN) buf[p] = u & 0x3FFFu;
                }
            }
            __syncthreads();
            if (snb > BUFN) { if (tid == 0) sfall = 1; }
            else if (w == 0) {
                // warp 0: bitwise binary search over low 14 bits for rem1-th largest
                const int nb = snb;
                const int nj = (nb + 31) >> 5;
                unsigned my[BUFN / 32];
                for (int j = 0; j < nj; j++)
                    my[j] = (lane + 32 * j < nb) ? buf[lane + 32 * j] : 0u;
                unsigned T = 0u;
#pragma unroll
                for (int bit = 13; bit >= 0; --bit) {
                    unsigned cT = T | (1u << bit);
                    int c = 0;
                    for (int j = 0; j < nj; j++)
                        c += __popc(__ballot_sync(0xffffffffu, my[j] >= cT));
                    if (c >= rem1) T = cT;
                }
                if (lane == 0) suT = FONE | (d0 << 14) | T;
            }
        }
        __syncthreads();

        if (!sfall) {
            // ---- final: sum/count of candidates strictly above threshold ----
            const float Tval = __uint_as_float(suT);
            float ls = 0.f; int lc = 0;
            for (int i = 0; i < mc; i++) {
                float v = seg[i];
                if (v > Tval) { ls += v; lc++; }
            }
#pragma unroll
            for (int o = 16; o; o >>= 1) {
                ls += __shfl_down_sync(0xffffffffu, ls, o);
                lc += __shfl_down_sync(0xffffffffu, lc, o);
            }
            if (lane == 0) { fred[w] = ls; ired[w] = lc; }
            __syncthreads();
            if (tid == 0) {
                float s = 0.f; int c = 0;
                for (int i = 0; i < NWARP; i++) { s += fred[i]; c += ired[i]; }
                g_avg[row] = (s + Tval * (float)(TOPK - c)) / (float)TOPK;
            }
            return;
        }
    }

    // ---- exact fallback: bitwise binary search over full 32-bit keys ----
    {
        unsigned T = 0u;
        for (int bit = 31; bit >= 0; --bit) {
            const unsigned cT = T | (1u << bit);
            int c = 0;
#pragma unroll 4
            for (int i = 0; i < HW / (4 * NT); i++) {
                float4 v = xin[tid + i * NT];
                c += (f2key(v.x) >= cT) + (f2key(v.y) >= cT)
                   + (f2key(v.z) >= cT) + (f2key(v.w) >= cT);
            }
#pragma unroll
            for (int o = 16; o; o >>= 1) c += __shfl_down_sync(0xffffffffu, c, o);
            if (lane == 0) ired[w] = c;
            __syncthreads();
            if (tid == 0) {
                int s = 0;
                for (int i = 0; i < NWARP; i++) s += ired[i];
                srem = s;
            }
            __syncthreads();
            if (srem >= TOPK) T = cT;
            __syncthreads();
        }
        float ls = 0.f; int lc = 0;
        float lmax2 = -3.402823466e38f;
#pragma unroll 4
        for (int i = 0; i < HW / (4 * NT); i++) {
            float4 v = xin[tid + i * NT];
            lmax2 = fmaxf(lmax2, fmaxf(fmaxf(v.x, v.y), fmaxf(v.z, v.w)));
            float vv[4] = {v.x, v.y, v.z, v.w};
#pragma unroll
            for (int j = 0; j < 4; j++) {
                unsigned kk = f2key(vv[j]);
                if (kk > T) { ls += vv[j]; lc++; }
            }
        }
#pragma unroll
        for (int o = 16; o; o >>= 1) {
            ls += __shfl_down_sync(0xffffffffu, ls, o);
            lc += __shfl_down_sync(0xffffffffu, lc, o);
            lmax2 = fmaxf(lmax2, __shfl_down_sync(0xffffffffu, lmax2, o));
        }
        if (lane == 0) { fred[w] = ls; ired[w] = lc; cand[w] = lmax2; }
        __syncthreads();
        if (tid == 0) {
            float s = 0.f; int c = 0; float m = cand[0];
            for (int i = 0; i < NWARP; i++) { s += fred[i]; c += ired[i]; m = fmaxf(m, cand[i]); }
            g_avg[row] = (s + key2f(T) * (float)(TOPK - c)) / (float)TOPK;
            g_maxv[row] = m;
        }
    }
}

// ---------------------------------------------------------------------------
// Kernel 2: tiny per-batch MLP -> g_scale
// ---------------------------------------------------------------------------
__global__ void mlp_kernel(const float* __restrict__ w1, const float* __restrict__ b1,
                           const float* __restrict__ w2, const float* __restrict__ b2) {
    __shared__ float avg[CC], mx[CC], h[2 * HID];
    const int b = blockIdx.x, c = threadIdx.x;
    avg[c] = g_avg[b * CC + c];
    mx[c]  = g_maxv[b * CC + c];
    __syncthreads();
    if (c < 2 * HID) {
        int j = c & (HID - 1);
        const float* pool = (c < HID) ? avg : mx;
        float s = b1[j];
#pragma unroll 8
        for (int i = 0; i < CC; i++) s += pool[i] * w1[i * HID + j];
        h[c] = fmaxf(s, 0.f);
    }
    __syncthreads();
    float s = 2.f * b2[c];
#pragma unroll
    for (int j = 0; j < HID; j++) s += (h[j] + h[HID + j]) * w2[j * CC + c];
    g_scale[b * CC + c] = 1.f / (1.f + __expf(-s));
}

// ---------------------------------------------------------------------------
// Kernel 3: y = x * scale[row]
// ---------------------------------------------------------------------------
__global__ __launch_bounds__(256) void scale_kernel(const float* __restrict__ x,
                                                    float* __restrict__ y) {
    const int row = blockIdx.x;
    const float s = g_scale[row];
    const float4* xi = (const float4*)(x + (size_t)row * HW);
    float4* yo = (float4*)(y + (size_t)row * HW);
    const int t = threadIdx.x;
#pragma unroll
    for (int i = 0; i < HW / (4 * 256); i++) {
        float4 v = xi[t + i * 256];
        v.x *= s; v.y *= s; v.z *= s; v.w *= s;
        yo[t + i * 256] = v;
    }
}

extern "C" void kernel_launch(void* const* d_in, const int* in_sizes, int n_in,
                              void* d_out, int out_size) {
    const float* x  = (const float*)d_in[0];
    const float* w1 = (const float*)d_in[1];
    const float* b1 = (const float*)d_in[2];
    const float* w2 = (const float*)d_in[3];
    const float* b2 = (const float*)d_in[4];
    float* y = (float*)d_out;

    topk_stats<<<ROWS, NT>>>(x);
    mlp_kernel<<<BB, CC>>>(w1, b1, w2, b2);
    scale_kernel<<<ROWS, 256>>>(x, y);
}

// round 17
// speedup vs baseline: 1.2847x; 1.2847x over previous
#include <cuda_runtime.h>

#define HW    16384      // H*W
#define ROWS  4096       // B*C
#define CC    128
#define BB    32
#define TOPK  1638       // round(16384 * 0.1)
#define HID   8
#define NT    256
#define NWARP 8
#define SLOT  26         // per-thread candidate slots (64 elems/thread, ~10 hits)
#define STRIDE 27        // odd: conflict-free segment+dump stores
#define NBH   1792       // histogram bins (7/thread); valid ids [0,1536]
#define BUFN  256        // threshold-bin buffer
#define T_LO  1.0f
#define FONE  0x3F800000u

__device__ float g_avg[ROWS];
__device__ float g_maxv[ROWS];
__device__ float g_scale[ROWS];

__device__ __forceinline__ unsigned f2key(float f) {
    unsigned u = __float_as_uint(f);
    return u ^ ((unsigned)((int)u >> 31) | 0x80000000u);
}
__device__ __forceinline__ float key2f(unsigned k) {
    unsigned u = k ^ (((int)k < 0) ? 0x80000000u : 0xFFFFFFFFu);
    return __uint_as_float(u);
}
__device__ __forceinline__ int vbin(float v) {
    return min((int)((__float_as_uint(v) - FONE) >> 14), 1536);
}
// packed u16-pair histogram read: bin b lives in word b>>1, half b&1
__device__ __forceinline__ int hget(const unsigned* hp, int b) {
    return (int)((hp[b >> 1] >> ((b & 1) * 16)) & 0xFFFFu);
}

// Suffix-count select over packed hist: bin b with s(b) >= rem > s(b+1).
__device__ __forceinline__ void suffix_select_p(const unsigned* hp, int rem,
                                                int* swarp, unsigned* sdigit,
                                                int* srem) {
    const int tid = threadIdx.x, lane = tid & 31, w = tid >> 5;
    const int BPT = NBH / NT;            // 7 bins per thread
    const int base = tid * BPT;
    int loc[NBH / NT];
    int tsum = 0;
#pragma unroll
    for (int i = 0; i < BPT; i++) { loc[i] = hget(hp, base + i); tsum += loc[i]; }
    int inc = tsum;                       // suffix over lanes >= lane
#pragma unroll
    for (int o = 1; o < 32; o <<= 1) {
        int v = __shfl_down_sync(0xffffffffu, inc, o);
        if (lane + o < 32) inc += v;
    }
    if (lane == 0) swarp[w] = inc;
    __syncthreads();
    if (tid < 32) {
        int v = (lane < NWARP) ? swarp[lane] : 0;
        int s = v;
#pragma unroll
        for (int o = 1; o < 32; o <<= 1) {
            int t = __shfl_down_sync(0xffffffffu, s, o);
            if (lane + o < 32) s += t;
        }
        if (lane < NWARP) swarp[lane] = s - v;   // exclusive suffix above this warp
    }
    __syncthreads();
    int s_next = (inc - tsum) + swarp[w];
#pragma unroll
    for (int i = BPT - 1; i >= 0; i--) {
        int s = loc[i] + s_next;
        if (s >= rem && s_next < rem) { *sdigit = (unsigned)(base + i); *srem = rem - s_next; }
        s_next = s;
    }
    __syncthreads();
}

// ---------------------------------------------------------------------------
// Pass 1: per-(b,c) top-k mean + max.
// Sweep: branch-free dump-slot compaction (conflict-free odd stride).
// Post-pass: max + packed histogram. Then suffix-select + 14-bit in-bin search.
// ---------------------------------------------------------------------------
__global__ __launch_bounds__(NT, 6) void topk_stats(const float* __restrict__ x) {
    __shared__ float    cand[NT * STRIDE];   // 27.6 KB per-thread segments (+dump)
    __shared__ unsigned histp[NBH / 2];      // 3.5 KB packed u16-pair histogram
    __shared__ unsigned buf[BUFN];           // 1 KB threshold-bin members (low 14 bits)
    __shared__ int      swarp[NWARP];
    __shared__ unsigned sdigit, suT;
    __shared__ int      srem, sfall, snb;
    __shared__ float    fred[NWARP];
    __shared__ int      ired[NWARP];

    const int tid = threadIdx.x, lane = tid & 31, w = tid >> 5;
    const int row = blockIdx.x;
    const float4* xin = (const float4*)(x + (size_t)row * HW);
    float* seg = cand + tid * STRIDE;

    // zero packed histogram (filled by post-pass)
#pragma unroll
    for (int i = tid; i < NBH / 2; i += NT) histp[i] = 0u;
    if (tid == 0) snb = 0;
    __syncthreads();

    // ---- sweep: branch-free compaction with dump slot ----
    int cnt = 0;
#pragma unroll 8
    for (int i = 0; i < HW / (4 * NT); i++) {
        float4 v = xin[tid + i * NT];
        int h0 = v.x > T_LO, h1 = v.y > T_LO, h2 = v.z > T_LO, h3 = v.w > T_LO;
        int p0 = cnt, p1 = p0 + h0, p2 = p1 + h1, p3 = p2 + h2;
        seg[h0 ? min(p0, SLOT) : SLOT] = v.x;
        seg[h1 ? min(p1, SLOT) : SLOT] = v.y;
        seg[h2 ? min(p2, SLOT) : SLOT] = v.z;
        seg[h3 ? min(p3, SLOT) : SLOT] = v.w;
        cnt = p3 + h3;
    }

    // ---- post-pass over real candidates: max + packed histogram ----
    const int mc = min(cnt, SLOT);
    float lmax = -3.402823466e38f;
    for (int i = 0; i < mc; i++) {
        float v = seg[i];
        lmax = fmaxf(lmax, v);
        int b = vbin(v);
        atomicAdd(&histp[b >> 1], (b & 1) ? 65536u : 1u);
    }

    int of = (cnt > SLOT) ? 1 : 0;
    int tot = cnt;
#pragma unroll
    for (int o = 16; o; o >>= 1) {
        lmax = fmaxf(lmax, __shfl_down_sync(0xffffffffu, lmax, o));
        tot += __shfl_down_sync(0xffffffffu, tot, o);
        of  |= __shfl_down_sync(0xffffffffu, of, o);
    }
    if (lane == 0) { fred[w] = lmax; ired[w] = tot; swarp[w] = of; }
    __syncthreads();
    if (tid == 0) {
        float m = fred[0]; int t = 0, o = 0;
        for (int i = 0; i < NWARP; i++) { m = fmaxf(m, fred[i]); t += ired[i]; o |= swarp[i]; }
        sfall = (o || t < TOPK);
        if (!sfall) g_maxv[row] = m;     // fast path: max is among candidates
    }
    __syncthreads();

    if (!sfall) {
        suffix_select_p(histp, TOPK, swarp, &sdigit, &srem);
        const unsigned d0 = sdigit; const int rem1 = srem;

        if (d0 >= 1536) { if (tid == 0) sfall = 1; }
        else {
            // collect threshold-bin members (low 14 bits) into buf
            for (int i = 0; i < mc; i++) {
                unsigned u = __float_as_uint(seg[i]);
                if ((u - FONE) >> 14 == d0) {
                    int p = atomicAdd(&snb, 1);
                    if (p < BUFN) buf[p] = u & 0x3FFFu;
                }
            }
            __syncthreads();
            if (snb > BUFN) { if (tid == 0) sfall = 1; }
            else if (w == 0) {
                // warp 0: bitwise binary search over low 14 bits for rem1-th largest
                const int nb = snb;
                const int nj = (nb + 31) >> 5;
                unsigned my[BUFN / 32];
                for (int j = 0; j < nj; j++)
                    my[j] = (lane + 32 * j < nb) ? buf[lane + 32 * j] : 0u;
                unsigned T = 0u;
#pragma unroll
                for (int bit = 13; bit >= 0; --bit) {
                    unsigned cT = T | (1u << bit);
                    int c = 0;
                    for (int j = 0; j < nj; j++)
                        c += __popc(__ballot_sync(0xffffffffu, my[j] >= cT));
                    if (c >= rem1) T = cT;
                }
                if (lane == 0) suT = FONE | (d0 << 14) | T;
            }
        }
        __syncthreads();

        if (!sfall) {
            // ---- final: sum/count of candidates strictly above threshold ----
            const float Tval = __uint_as_float(suT);
            float ls = 0.f; int lc = 0;
            for (int i = 0; i < mc; i++) {
                float v = seg[i];
                if (v > Tval) { ls += v; lc++; }
            }
#pragma unroll
            for (int o = 16; o; o >>= 1) {
                ls += __shfl_down_sync(0xffffffffu, ls, o);
                lc += __shfl_down_sync(0xffffffffu, lc, o);
            }
            if (lane == 0) { fred[w] = ls; ired[w] = lc; }
            __syncthreads();
            if (tid == 0) {
                float s = 0.f; int c = 0;
                for (int i = 0; i < NWARP; i++) { s += fred[i]; c += ired[i]; }
                g_avg[row] = (s + Tval * (float)(TOPK - c)) / (float)TOPK;
            }
            return;
        }
    }

    // ---- exact fallback: bitwise binary search over full 32-bit keys ----
    {
        unsigned T = 0u;
        for (int bit = 31; bit >= 0; --bit) {
            const unsigned cT = T | (1u << bit);
            int c = 0;
#pragma unroll 4
            for (int i = 0; i < HW / (4 * NT); i++) {
                float4 v = xin[tid + i * NT];
                c += (f2key(v.x) >= cT) + (f2key(v.y) >= cT)
                   + (f2key(v.z) >= cT) + (f2key(v.w) >= cT);
            }
#pragma unroll
            for (int o = 16; o; o >>= 1) c += __shfl_down_sync(0xffffffffu, c, o);
            if (lane == 0) ired[w] = c;
            __syncthreads();
            if (tid == 0) {
                int s = 0;
                for (int i = 0; i < NWARP; i++) s += ired[i];
                srem = s;
            }
            __syncthreads();
            if (srem >= TOPK) T = cT;
            __syncthreads();
        }
        float ls = 0.f; int lc = 0;
        float lmax2 = -3.402823466e38f;
#pragma unroll 4
        for (int i = 0; i < HW / (4 * NT); i++) {
            float4 v = xin[tid + i * NT];
            lmax2 = fmaxf(lmax2, fmaxf(fmaxf(v.x, v.y), fmaxf(v.z, v.w)));
            float vv[4] = {v.x, v.y, v.z, v.w};
#pragma unroll
            for (int j = 0; j < 4; j++) {
                unsigned kk = f2key(vv[j]);
                if (kk > T) { ls += vv[j]; lc++; }
            }
        }
#pragma unroll
        for (int o = 16; o; o >>= 1) {
            ls += __shfl_down_sync(0xffffffffu, ls, o);
            lc += __shfl_down_sync(0xffffffffu, lc, o);
            lmax2 = fmaxf(lmax2, __shfl_down_sync(0xffffffffu, lmax2, o));
        }
        if (lane == 0) { fred[w] = ls; ired[w] = lc; cand[w] = lmax2; }
        __syncthreads();
        if (tid == 0) {
            float s = 0.f; int c = 0; float m = cand[0];
            for (int i = 0; i < NWARP; i++) { s += fred[i]; c += ired[i]; m = fmaxf(m, cand[i]); }
            g_avg[row] = (s + key2f(T) * (float)(TOPK - c)) / (float)TOPK;
            g_maxv[row] = m;
        }
    }
}

// ---------------------------------------------------------------------------
// Kernel 2: tiny per-batch MLP -> g_scale
// ---------------------------------------------------------------------------
__global__ void mlp_kernel(const float* __restrict__ w1, const float* __restrict__ b1,
                           const float* __restrict__ w2, const float* __restrict__ b2) {
    __shared__ float avg[CC], mx[CC], h[2 * HID];
    const int b = blockIdx.x, c = threadIdx.x;
    avg[c] = g_avg[b * CC + c];
    mx[c]  = g_maxv[b * CC + c];
    __syncthreads();
    if (c < 2 * HID) {
        int j = c & (HID - 1);
        const float* pool = (c < HID) ? avg : mx;
        float s = b1[j];
#pragma unroll 8
        for (int i = 0; i < CC; i++) s += pool[i] * w1[i * HID + j];
        h[c] = fmaxf(s, 0.f);
    }
    __syncthreads();
    float s = 2.f * b2[c];
#pragma unroll
    for (int j = 0; j < HID; j++) s += (h[j] + h[HID + j]) * w2[j * CC + c];
    g_scale[b * CC + c] = 1.f / (1.f + __expf(-s));
}

// ---------------------------------------------------------------------------
// Kernel 3: y = x * scale[row]
// ---------------------------------------------------------------------------
__global__ __launch_bounds__(256) void scale_kernel(const float* __restrict__ x,
                                                    float* __restrict__ y) {
    const int row = blockIdx.x;
    const float s = g_scale[row];
    const float4* xi = (const float4*)(x + (size_t)row * HW);
    float4* yo = (float4*)(y + (size_t)row * HW);
    const int t = threadIdx.x;
#pragma unroll
    for (int i = 0; i < HW / (4 * 256); i++) {
        float4 v = xi[t + i * 256];
        v.x *= s; v.y *= s; v.z *= s; v.w *= s;
        yo[t + i * 256] = v;
    }
}

extern "C" void kernel_launch(void* const* d_in, const int* in_sizes, int n_in,
                              void* d_out, int out_size) {
    const float* x  = (const float*)d_in[0];
    const float* w1 = (const float*)d_in[1];
    const float* b1 = (const float*)d_in[2];
    const float* w2 = (const float*)d_in[3];
    const float* b2 = (const float*)d_in[4];
    float* y = (float*)d_out;

    topk_stats<<<ROWS, NT>>>(x);
    mlp_kernel<<<BB, CC>>>(w1, b1, w2, b2);
    scale_kernel<<<ROWS, 256>>>(x, y);
}